// round 16
// baseline (speedup 1.0000x reference)
#include <cuda_runtime.h>
#include <cuda_fp16.h>
#include <cstdint>
#include <math.h>

#define Bn   2
#define Tn   1024
#define Cn   1024
#define Hn   16
#define HSn  64
#define TTn  1024
#define FFNn 4096
#define EPSn 1e-6f

// ---------------- scratch ----------------
__device__ __half g_xs [Bn*Tn*Cn];
__device__ __half g_q  [Bn*Tn*Cn];
__device__ __half g_k  [Bn*Tn*Cn];
__device__ __half g_v  [Bn*Tn*Cn];          // k-pair packed per (b,h)
__device__ __half g_att [Bn*Hn*Tn*Tn];      // aliased as fp32 split-K partials
__device__ __half g_att2[Bn*Hn*Tn*Tn];
__device__ __half g_y  [Bn*Tn*Cn];
__device__ float  g_x1 [Bn*Tn*Cn];
__device__ __half g_xm [Bn*Tn*Cn];
__device__ __half g_gv [Bn*Tn*FFNn];
__device__ uint32_t g_wh[8*1024*1024];      // weights as half [n][k], 32MB

// half-element offsets into g_wh
#define HOFF_Q   0u
#define HOFF_K   (1u<<20)
#define HOFF_V   (2u<<20)
#define HOFF_O   (3u<<20)
#define HOFF_GK  (4u<<20)
#define HOFF_GV  (8u<<20)
#define HOFF_GW  (12u<<20)

// ---------------- helpers ----------------
__device__ __forceinline__ void mma_fp16(float* d, const uint32_t* a, const uint32_t* b) {
    asm volatile(
        "mma.sync.aligned.m16n8k16.row.col.f32.f16.f16.f32 "
        "{%0,%1,%2,%3}, {%4,%5,%6,%7}, {%8,%9}, {%0,%1,%2,%3};"
        : "+f"(d[0]), "+f"(d[1]), "+f"(d[2]), "+f"(d[3])
        : "r"(a[0]), "r"(a[1]), "r"(a[2]), "r"(a[3]), "r"(b[0]), "r"(b[1]));
}
__device__ __forceinline__ void ldmat4(uint32_t* r, uint32_t addr) {
    asm volatile(
        "ldmatrix.sync.aligned.m8n8.x4.shared.b16 {%0,%1,%2,%3}, [%4];"
        : "=r"(r[0]), "=r"(r[1]), "=r"(r[2]), "=r"(r[3]) : "r"(addr));
}
__device__ __forceinline__ uint32_t smem_u32(const void* p) {
    uint32_t a;
    asm("{ .reg .u64 t; cvta.to.shared.u64 t, %1; cvt.u32.u64 %0, t; }"
        : "=r"(a) : "l"(p));
    return a;
}
__device__ __forceinline__ void cp16(uint32_t dst, const void* src) {
    asm volatile("cp.async.ca.shared.global [%0], [%1], 16;" :: "r"(dst), "l"(src));
}
__device__ __forceinline__ void cp_commit() {
    asm volatile("cp.async.commit_group;" ::: "memory");
}
template<int N> __device__ __forceinline__ void cp_wait() {
    asm volatile("cp.async.wait_group %0;" :: "n"(N) : "memory");
}

// ---------------- weight conversion: W[k][n] f32 -> Wt[n][k] half -----------
struct W4 { const float* w[4]; };

__device__ __forceinline__ void transpose_tile(const float* __restrict__ W,
                                               __half* __restrict__ dst,
                                               int K, int N) {
    __shared__ float tile[32][33];
    int bx = blockIdx.x * 32;  // n
    int by = blockIdx.y * 32;  // k
    int tx = threadIdx.x, ty = threadIdx.y;
#pragma unroll
    for (int i = 0; i < 32; i += 8)
        tile[ty + i][tx] = W[(size_t)(by + ty + i) * N + bx + tx];
    __syncthreads();
#pragma unroll
    for (int i = 0; i < 32; i += 8)
        dst[(size_t)(bx + ty + i) * K + by + tx] = __float2half(tile[tx][ty + i]);
}

__global__ void convT_cc(W4 ws) {
    transpose_tile(ws.w[blockIdx.z],
                   (__half*)g_wh + (size_t)blockIdx.z * (1u << 20), Cn, Cn);
}
__global__ void convT_cf(const float* W0, const float* W1) {
    transpose_tile(blockIdx.z ? W1 : W0,
                   (__half*)g_wh + HOFF_GK + (size_t)blockIdx.z * (4u << 20),
                   Cn, FFNn);
}
__global__ void convT_gw(const float* W) {
    transpose_tile(W, (__half*)g_wh + HOFF_GW, FFNn, Cn);
}

// ---------------- fast row reduce ----------------
__device__ __forceinline__ void row_stats(float4 v4, float& mean, float& rstd,
                                          float* red) {
    int tid = threadIdx.x, lane = tid & 31, w = tid >> 5;
    float s  = v4.x + v4.y + v4.z + v4.w;
    float s2 = v4.x*v4.x + v4.y*v4.y + v4.z*v4.z + v4.w*v4.w;
#pragma unroll
    for (int o = 16; o; o >>= 1) {
        s  += __shfl_xor_sync(0xFFFFFFFFu, s,  o);
        s2 += __shfl_xor_sync(0xFFFFFFFFu, s2, o);
    }
    if (lane == 0) { red[w] = s; red[8 + w] = s2; }
    __syncthreads();
    if (tid == 0) {
        float a = 0.f, b2 = 0.f;
#pragma unroll
        for (int i = 0; i < 8; i++) { a += red[i]; b2 += red[8 + i]; }
        red[16] = a; red[17] = b2;
    }
    __syncthreads();
    mean = red[16] / Cn;
    rstd = rsqrtf(red[17] / Cn - mean * mean + EPSn);
}

// ---------------- LN1 + time_shift_half ----------------
__global__ __launch_bounds__(256)
void ln1_shift_kernel(const float* __restrict__ x,
                      const float* __restrict__ g,
                      const float* __restrict__ b) {
    __shared__ float red[18];
    int bt = blockIdx.x;
    int bb = bt >> 10, t = bt & (Tn - 1);
    int c = threadIdx.x * 4;
    float4 v4 = *(const float4*)(x + (size_t)bt * Cn + c);
    float mean, rstd;
    row_stats(v4, mean, rstd, red);
    float4 g4 = *(const float4*)(g + c);
    float4 b4 = *(const float4*)(b + c);
    __half2 h01 = __floats2half2_rn((v4.x - mean) * rstd * g4.x + b4.x,
                                    (v4.y - mean) * rstd * g4.y + b4.y);
    __half2 h23 = __floats2half2_rn((v4.z - mean) * rstd * g4.z + b4.z,
                                    (v4.w - mean) * rstd * g4.w + b4.w);
    uint2 pk; pk.x = *(uint32_t*)&h01; pk.y = *(uint32_t*)&h23;
    if (c < Cn / 2) {
        if (t + 1 < Tn)
            *(uint2*)(g_xs + ((size_t)bb * Tn + t + 1) * Cn + c) = pk;
        if (t == 0)
            *(uint2*)(g_xs + (size_t)bb * Tn * Cn + c) = make_uint2(0, 0);
    } else {
        *(uint2*)(g_xs + (size_t)bt * Cn + c) = pk;
    }
}

// ---------------- fused fin_wo + LN2 ----------------
__global__ __launch_bounds__(256)
void ln2_fused(const float* __restrict__ P, const float* __restrict__ bo,
               const float* __restrict__ gamma, const float* __restrict__ x,
               const float* __restrict__ g, const float* __restrict__ b) {
    __shared__ float red[18];
    int bt = blockIdx.x;
    int t = bt & (Tn - 1);
    int c = threadIdx.x * 4;
    const size_t half = (size_t)(Bn * Tn) * Cn;
    size_t i = (size_t)bt * Cn + c;
    float4 a4 = *(const float4*)(P + i);
    float4 p4 = *(const float4*)(P + half + i);
    float4 x4 = *(const float4*)(x + i);
    float4 bo4 = *(const float4*)(bo + c);
    float gm = gamma[t];
    float4 v4;
    v4.x = (a4.x + p4.x + bo4.x) * gm + x4.x;
    v4.y = (a4.y + p4.y + bo4.y) * gm + x4.y;
    v4.z = (a4.z + p4.z + bo4.z) * gm + x4.z;
    v4.w = (a4.w + p4.w + bo4.w) * gm + x4.w;
    *(float4*)(g_x1 + i) = v4;
    float mean, rstd;
    row_stats(v4, mean, rstd, red);
    float4 g4 = *(const float4*)(g + c);
    float4 b4 = *(const float4*)(b + c);
    __half2 h01 = __floats2half2_rn((v4.x - mean) * rstd * g4.x + b4.x,
                                    (v4.y - mean) * rstd * g4.y + b4.y);
    __half2 h23 = __floats2half2_rn((v4.z - mean) * rstd * g4.z + b4.z,
                                    (v4.w - mean) * rstd * g4.w + b4.w);
    uint2 pk; pk.x = *(uint32_t*)&h01; pk.y = *(uint32_t*)&h23;
    *(uint2*)(g_xm + i) = pk;
}

// ======== fp16 GEMM core (128x128, 8 warps, K-chunk 64, 2-stage, ldmatrix) ==
#define EPI_NONE  0
#define EPI_QKV   1

#define AW 36                      // A row stride (words): 32 data + 4 pad
#define BW2 36                     // B row stride (words): 32 data + 4 pad
#define ABUFW (128*AW)             // 4608 words
#define BBUFW2 (128*BW2)           // 4608 words
#define GEMM_SMEMW (2*(ABUFW+BBUFW2))   // 18432 words = 73728 B

template<int MODE>
__device__ __forceinline__ void gemm_body(
    uint32_t* usm,
    const __half* __restrict__ A, const __half* __restrict__ Bh,
    const float* __restrict__ bias, void* __restrict__ Cv,
    int N, int Kfull, int koff, int kspan,
    int row0, int col0, int qkvmode)
{
    uint32_t sb = smem_u32(usm);
    int tid = threadIdx.x;
    int lane = tid & 31, wid = tid >> 5;
    int wm = wid >> 2, wn = wid & 3;
    int lg = lane >> 2, lq = lane & 3;

    float acc[4][4][4] = {};

    int aw = (tid & 1) * 16;       // word quarter within 32-word row
    const __half* Ab = A + (size_t)(row0 + (tid >> 1)) * Kfull + koff + aw * 2;
    const __half* Bb = Bh + (size_t)(col0 + (tid >> 1)) * Kfull + koff + aw * 2;
    uint32_t adst0 = sb + (uint32_t)(((tid >> 1) * AW + aw) * 4);
    uint32_t bdst0 = sb + (uint32_t)((2 * ABUFW + (tid >> 1) * BW2 + aw) * 4);

    // ldmatrix bases
    uint32_t albase = sb + (uint32_t)(((wm * 64 + (lane & 15)) * AW + (lane >> 4) * 4) * 4);
    uint32_t blbase = sb + (uint32_t)((2 * ABUFW + (wn * 32 + (lane & 15)) * BW2 + (lane >> 4) * 4) * 4);

    const int nch = kspan >> 6;

#define GISS(ci) do { \
    int _p = (ci) & 1; int _k0 = (ci) << 6; \
    uint32_t _ad = adst0 + _p * ABUFW * 4; \
    const __half* _a = Ab + _k0; \
    cp16(_ad,      _a);      cp16(_ad + 16, _a + 8); \
    cp16(_ad + 32, _a + 16); cp16(_ad + 48, _a + 24); \
    uint32_t _bd = bdst0 + _p * BBUFW2 * 4; \
    const __half* _b = Bb + _k0; \
    cp16(_bd,      _b);      cp16(_bd + 16, _b + 8); \
    cp16(_bd + 32, _b + 16); cp16(_bd + 48, _b + 24); \
} while (0)

    GISS(0); cp_commit();

    for (int ci = 0; ci < nch; ci++) {
        cp_wait<0>();
        __syncthreads();
        if (ci + 1 < nch) { GISS(ci + 1); cp_commit(); }

        uint32_t al = albase + (ci & 1) * (ABUFW * 4);
        uint32_t bl = blbase + (ci & 1) * (BBUFW2 * 4);
#pragma unroll
        for (int ks = 0; ks < 4; ks++) {
            int kbw = ks * 8;
            uint32_t af[4][4], bp[2][4];
#pragma unroll
            for (int mi = 0; mi < 4; mi++)
                ldmat4(af[mi], al + (uint32_t)((mi * 16 * AW + kbw) * 4));
#pragma unroll
            for (int j = 0; j < 2; j++)
                ldmat4(bp[j], bl + (uint32_t)((j * 16 * BW2 + kbw) * 4));
#pragma unroll
            for (int mi = 0; mi < 4; mi++)
#pragma unroll
                for (int ni = 0; ni < 4; ni++) {
                    uint32_t bf[2] = { bp[ni >> 1][ni & 1], bp[ni >> 1][2 + (ni & 1)] };
                    mma_fp16(acc[mi][ni], af[mi], bf);
                }
        }
        __syncthreads();
    }
#undef GISS

    if (MODE == EPI_QKV) {
        __half* out = (__half*)Cv;
#pragma unroll
        for (int mi = 0; mi < 4; mi++) {
#pragma unroll
            for (int hf = 0; hf < 2; hf++) {
                int r = row0 + wm * 64 + mi * 16 + lg + hf * 8;
                int bI = r >> 10, t = r & (Tn - 1);
                float v[4][2];
#pragma unroll
                for (int ni = 0; ni < 4; ni++) {
                    int c = col0 + wn * 32 + ni * 8 + lq * 2;
                    v[ni][0] = acc[mi][ni][hf * 2 + 0] + bias[c];
                    v[ni][1] = acc[mi][ni][hf * 2 + 1] + bias[c + 1];
                }
                if (qkvmode == 0 && !(wn & 1)) {
#pragma unroll
                    for (int ni = 0; ni < 2; ni++) {
                        int d0 = ni * 8 + lq * 2;
#pragma unroll
                        for (int j = 0; j < 2; j++) {
                            float ang = (float)t * exp2f(-0.625f * (float)(d0 + j));
                            float sv, cv;
                            sincosf(ang, &sv, &cv);
                            float a = v[ni][j], b2 = v[ni + 2][j];
                            v[ni][j]     = a * cv - b2 * sv;
                            v[ni + 2][j] = b2 * cv + a * sv;
                        }
                    }
                }
#pragma unroll
                for (int ni = 0; ni < 4; ni++) {
                    int c = col0 + wn * 32 + ni * 8 + lq * 2;
                    int h = c >> 6, d = c & 63;
                    size_t base = ((size_t)bI * Hn + h) * ((size_t)Tn * HSn);
                    __half2 h2 = __floats2half2_rn(v[ni][0], v[ni][1]);
                    if (qkvmode != 2) {
                        *(__half2*)(out + base + (size_t)t * HSn + d) = h2;
                    } else {
                        size_t w = base + ((size_t)(t >> 1) * HSn + d) * 2 + (t & 1);
                        out[w]     = __low2half(h2);
                        out[w + 2] = __high2half(h2);
                    }
                }
            }
        }
    } else {
        float* out = (float*)Cv;
#pragma unroll
        for (int mi = 0; mi < 4; mi++)
#pragma unroll
            for (int ni = 0; ni < 4; ni++)
#pragma unroll
                for (int hf = 0; hf < 2; hf++) {
                    int r = row0 + wm * 64 + mi * 16 + lg + hf * 8;
                    int c = col0 + wn * 32 + ni * 8 + lq * 2;
                    size_t oi = (size_t)r * N + c;
                    out[oi]     = acc[mi][ni][hf * 2 + 0];
                    out[oi + 1] = acc[mi][ni][hf * 2 + 1];
                }
    }
}

struct QKVArgs {
    const float *b0, *b1, *b2;
    __half *q, *k, *v;
};

__global__ __launch_bounds__(256, 2)
void gemm_qkv(const __half* __restrict__ A, QKVArgs a) {
    extern __shared__ uint32_t usm[];
    int z = blockIdx.z;
    const __half* Bh = (const __half*)g_wh + (size_t)z * (1u << 20);
    const float* bias = (z == 0) ? a.b0 : (z == 1) ? a.b1 : a.b2;
    __half* out = (z == 0) ? a.q : (z == 1) ? a.k : a.v;
    gemm_body<EPI_QKV>(usm, A, Bh, bias, out, Cn, Cn, 0, Cn,
                       blockIdx.y * 128, blockIdx.x * 128, (z == 2) ? 2 : 0);
}

__global__ __launch_bounds__(256, 2)
void gemm_splitk(const __half* __restrict__ A, const __half* __restrict__ Bh,
                 float* __restrict__ P, int N, int Kfull) {
    extern __shared__ uint32_t usm[];
    int z = blockIdx.z;
    int kh = Kfull >> 1;
    float* out = P + (size_t)z * (Bn * Tn) * Cn;
    gemm_body<EPI_NONE>(usm, A, Bh, nullptr, out, N, Kfull, z * kh, kh,
                        blockIdx.y * 128, blockIdx.x * 128, -1);
}

// ================= dual FFN-up GEMM (K-chunk 64, 2-stage, ldmatrix) =========
#define DUAL_SMEMW (2*ABUFW + 4*BBUFW2)   // 27648 words = 110592 B

__global__ __launch_bounds__(256)
void gemm_ffn_dual(const __half* __restrict__ A,
                   const __half* __restrict__ B1h,
                   const __half* __restrict__ B2h,
                   const float* __restrict__ bias1,
                   const float* __restrict__ bias2,
                   __half* __restrict__ C) {
    extern __shared__ uint32_t usm[];
    const int K = Cn;
    uint32_t sb = smem_u32(usm);
    int tid = threadIdx.x;
    int lane = tid & 31, wid = tid >> 5;
    int wm = wid >> 2, wn = wid & 3;
    int lg = lane >> 2, lq = lane & 3;
    int row0 = blockIdx.y * 128, col0 = blockIdx.x * 128;

    float acc1[4][4][4] = {};
    float acc2[4][4][4] = {};

    int aw = (tid & 1) * 16;
    const __half* Ab  = A   + (size_t)(row0 + (tid >> 1)) * K + aw * 2;
    const __half* B1b = B1h + (size_t)(col0 + (tid >> 1)) * K + aw * 2;
    const __half* B2b = B2h + (size_t)(col0 + (tid >> 1)) * K + aw * 2;
    uint32_t adst0  = sb + (uint32_t)(((tid >> 1) * AW + aw) * 4);
    uint32_t b1dst0 = sb + (uint32_t)((2 * ABUFW + (tid >> 1) * BW2 + aw) * 4);
    uint32_t b2dst0 = b1dst0 + 2 * BBUFW2 * 4;

    uint32_t albase  = sb + (uint32_t)(((wm * 64 + (lane & 15)) * AW + (lane >> 4) * 4) * 4);
    uint32_t b1lbase = sb + (uint32_t)((2 * ABUFW + (wn * 32 + (lane & 15)) * BW2 + (lane >> 4) * 4) * 4);
    uint32_t b2lbase = b1lbase + 2 * BBUFW2 * 4;

    const int nch = K >> 6;

#define DISS(ci) do { \
    int _p = (ci) & 1; int _k0 = (ci) << 6; \
    uint32_t _ad = adst0 + _p * ABUFW * 4; \
    const __half* _a = Ab + _k0; \
    cp16(_ad,      _a);      cp16(_ad + 16, _a + 8); \
    cp16(_ad + 32, _a + 16); cp16(_ad + 48, _a + 24); \
    uint32_t _b1d = b1dst0 + _p * BBUFW2 * 4; \
    const __half* _b1 = B1b + _k0; \
    cp16(_b1d,      _b1);      cp16(_b1d + 16, _b1 + 8); \
    cp16(_b1d + 32, _b1 + 16); cp16(_b1d + 48, _b1 + 24); \
    uint32_t _b2d = b2dst0 + _p * BBUFW2 * 4; \
    const __half* _b2 = B2b + _k0; \
    cp16(_b2d,      _b2);      cp16(_b2d + 16, _b2 + 8); \
    cp16(_b2d + 32, _b2 + 16); cp16(_b2d + 48, _b2 + 24); \
} while (0)

    DISS(0); cp_commit();

    for (int ci = 0; ci < nch; ci++) {
        cp_wait<0>();
        __syncthreads();
        if (ci + 1 < nch) { DISS(ci + 1); cp_commit(); }

        uint32_t al  = albase  + (ci & 1) * (ABUFW * 4);
        uint32_t b1l = b1lbase + (ci & 1) * (BBUFW2 * 4);
        uint32_t b2l = b2lbase + (ci & 1) * (BBUFW2 * 4);
#pragma unroll
        for (int ks = 0; ks < 4; ks++) {
            int kbw = ks * 8;
            uint32_t af[4][4], bp1[2][4], bp2[2][4];
#pragma unroll
            for (int mi = 0; mi < 4; mi++)
                ldmat4(af[mi], al + (uint32_t)((mi * 16 * AW + kbw) * 4));
#pragma unroll
            for (int j = 0; j < 2; j++) {
                ldmat4(bp1[j], b1l + (uint32_t)((j * 16 * BW2 + kbw) * 4));
                ldmat4(bp2[j], b2l + (uint32_t)((j * 16 * BW2 + kbw) * 4));
            }
#pragma unroll
            for (int mi = 0; mi < 4; mi++)
#pragma unroll
                for (int ni = 0; ni < 4; ni++) {
                    uint32_t bf1[2] = { bp1[ni >> 1][ni & 1], bp1[ni >> 1][2 + (ni & 1)] };
                    uint32_t bf2[2] = { bp2[ni >> 1][ni & 1], bp2[ni >> 1][2 + (ni & 1)] };
                    mma_fp16(acc1[mi][ni], af[mi], bf1);
                    mma_fp16(acc2[mi][ni], af[mi], bf2);
                }
        }
        __syncthreads();
    }
#undef DISS

#pragma unroll
    for (int mi = 0; mi < 4; mi++) {
#pragma unroll
        for (int ni = 0; ni < 4; ni++) {
#pragma unroll
            for (int hf = 0; hf < 2; hf++) {
                int r = row0 + wm * 64 + mi * 16 + lg + hf * 8;
                int c = col0 + wn * 32 + ni * 8 + lq * 2;
                float k0 = acc1[mi][ni][hf * 2 + 0] + bias1[c];
                float k1 = acc1[mi][ni][hf * 2 + 1] + bias1[c + 1];
                float m0 = acc2[mi][ni][hf * 2 + 0] + bias2[c];
                float m1 = acc2[mi][ni][hf * 2 + 1] + bias2[c + 1];
                float gl0 = 0.5f * k0 * (1.f + erff(k0 * 0.70710678118654752f));
                float gl1 = 0.5f * k1 * (1.f + erff(k1 * 0.70710678118654752f));
                *(__half2*)(C + (size_t)r * FFNn + c) =
                    __floats2half2_rn(gl0 * m0, gl1 * m1);
            }
        }
    }
}

// finalize Wgw
__global__ void fin_wgw(const float* __restrict__ P, const float* __restrict__ bgw,
                        const float* __restrict__ x1, float* __restrict__ out) {
    size_t i = ((size_t)blockIdx.x * 256 + threadIdx.x) * 4;
    const size_t half = (size_t)(Bn * Tn) * Cn;
    float4 a = *(const float4*)(P + i);
    float4 b = *(const float4*)(P + half + i);
    float4 r = *(const float4*)(x1 + i);
    int c = (int)(i & (Cn - 1));
    float4 o;
    o.x = a.x + b.x + bgw[c]     + r.x;
    o.y = a.y + b.y + bgw[c + 1] + r.y;
    o.z = a.z + b.z + bgw[c + 2] + r.z;
    o.w = a.w + b.w + bgw[c + 3] + r.w;
    *(float4*)(out + i) = o;
}

// ---------------- scores via fp16 mma (NT, triangular grid, ldmatrix) ------
#define SW 36
__global__ __launch_bounds__(256, 2)
void scores_mma() {
    int i = blockIdx.x;
    int tt = (int)((sqrtf(8.f * (float)i + 1.f) - 1.f) * 0.5f);
    while ((tt + 1) * (tt + 2) / 2 <= i) tt++;
    while (tt * (tt + 1) / 2 > i) tt--;
    int ut = i - tt * (tt + 1) / 2;
    int z = blockIdx.y;
    int row0 = tt * 128, col0 = ut * 128;
    const __half* q = g_q + (size_t)z * Tn * HSn;
    const __half* k = g_k + (size_t)z * Tn * HSn;

    __shared__ uint32_t sq[128 * SW];
    __shared__ uint32_t sk[128 * SW];

    int tid = threadIdx.x;
    int lane = tid & 31, wid = tid >> 5;
    int wm = wid >> 2, wn = wid & 3;

#pragma unroll
    for (int it = 0; it < 4; it++) {
        int id = it * 256 + tid;
        int row = id >> 3, c8 = id & 7;
        *(uint4*)&sq[row * SW + c8 * 4] =
            *(const uint4*)(q + (size_t)(row0 + row) * HSn + c8 * 8);
        *(uint4*)&sk[row * SW + c8 * 4] =
            *(const uint4*)(k + (size_t)(col0 + row) * HSn + c8 * 8);
    }
    __syncthreads();

    uint32_t sqb = smem_u32(sq);
    uint32_t skb = smem_u32(sk);
    uint32_t qal = sqb + (uint32_t)(((wm * 64 + (lane & 15)) * SW + (lane >> 4) * 4) * 4);
    uint32_t kal = skb + (uint32_t)(((wn * 32 + (lane & 15)) * SW + (lane >> 4) * 4) * 4);

    float acc[4][4][4] = {};
#pragma unroll
    for (int ks = 0; ks < 4; ks++) {
        int kbw = ks * 8;
        uint32_t af[4][4], bp[2][4];
#pragma unroll
        for (int mi = 0; mi < 4; mi++)
            ldmat4(af[mi], qal + (uint32_t)((mi * 16 * SW + kbw) * 4));
#pragma unroll
        for (int j = 0; j < 2; j++)
            ldmat4(bp[j], kal + (uint32_t)((j * 16 * SW + kbw) * 4));
#pragma unroll
        for (int mi = 0; mi < 4; mi++)
#pragma unroll
            for (int ni = 0; ni < 4; ni++) {
                uint32_t bf[2] = { bp[ni >> 1][ni & 1], bp[ni >> 1][2 + (ni & 1)] };
                mma_fp16(acc[mi][ni], af[mi], bf);
            }
    }

    int lg = lane >> 2, lq = lane & 3;
    __half* out = g_att + (size_t)z * Tn * Tn;
#pragma unroll
    for (int mi = 0; mi < 4; mi++)
#pragma unroll
        for (int ni = 0; ni < 4; ni++)
#pragma unroll
            for (int hf = 0; hf < 2; hf++) {
                int r = row0 + wm * 64 + mi * 16 + lg + hf * 8;
                int c = col0 + wn * 32 + ni * 8 + lq * 2;
                *(__half2*)(out + (size_t)r * Tn + c) =
                    __floats2half2_rn(acc[mi][ni][hf * 2 + 0] * 0.125f,
                                      acc[mi][ni][hf * 2 + 1] * 0.125f);
            }
}

// ---------------- fused softmax (causal) * w + head-mix ----------------
#define SMIX_SMEM ((Hn*Tn + 256) * 4)
__global__ __launch_bounds__(256)
void softmax_mix(const float* __restrict__ time_w,
                 const float* __restrict__ alpha,
                 const float* __restrict__ beta,
                 const float* __restrict__ Wmix) {
    extern __shared__ float sm[];
    float* p  = sm;
    float* wm = sm + Hn * Tn;
    int t = blockIdx.x, b = blockIdx.y;
    int tid = threadIdx.x, lane = tid & 31, w = tid >> 5;
    if (tid < 256) wm[tid] = Wmix[tid];
    int len = t + 1;

#pragma unroll
    for (int hh = 0; hh < 2; hh++) {
        int h = w * 2 + hh;
        const __half* src = g_att + (((size_t)b * Hn + h) * Tn + t) * Tn;
        float* ph = p + h * Tn;
        float mx = -1e30f;
        for (int u = lane; u < len; u += 32) {
            float v = __half2float(src[u]); ph[u] = v; mx = fmaxf(mx, v);
        }
#pragma unroll
        for (int o = 16; o; o >>= 1) mx = fmaxf(mx, __shfl_xor_sync(0xFFFFFFFFu, mx, o));
        float sum = 0.f;
        for (int u = lane; u < len; u += 32) {
            float e = expf(ph[u] - mx); ph[u] = e; sum += e;
        }
#pragma unroll
        for (int o = 16; o; o >>= 1) sum += __shfl_xor_sync(0xFFFFFFFFu, sum, o);
        float inv = 1.f / sum;
        float bt = beta[h * Tn + t];
        const float* twr = time_w + h * TTn + (TTn - 1 - t);
        const float* alr = alpha + h * Tn;
        for (int u = lane; u < len; u += 32)
            ph[u] *= inv * twr[u] * alr[u] * bt;
    }
    __syncthreads();

    int zend = (t / 128) * 128 + 128;
    const size_t stride = (size_t)Tn * Tn;
    for (int u = tid; u < zend; u += 256) {
        size_t obase = (((size_t)b * Hn) * Tn + t) * Tn + u;
        if (u < len) {
            float vals[Hn];
#pragma unroll
            for (int j = 0; j < Hn; j++) vals[j] = p[j * Tn + u];
#pragma unroll
            for (int i = 0; i < Hn; i++) {
                float s = 0.f;
#pragma unroll
                for (int j = 0; j < Hn; j++) s += wm[i * Hn + j] * vals[j];
                g_att2[obase + i * stride] = __float2half(s);
            }
        } else {
#pragma unroll
            for (int i = 0; i < Hn; i++)
                g_att2[obase + i * stride] = __float2half(0.f);
        }
    }
}

// ---------------- y = att2 @ v via fp16 mma (ldmatrix A) --------------------
#define AVW 20
#define VW 72
__global__ __launch_bounds__(256, 2)
void av_mma() {
    __shared__ uint32_t sa2[128 * AVW];
    __shared__ uint32_t sv [16 * VW];
    int tt = blockIdx.x;
    int z  = blockIdx.y;
    int row0 = tt * 128;
    const __half* Am = g_att2 + (size_t)z * Tn * Tn;
    const uint32_t* Vw = (const uint32_t*)g_v + (size_t)z * (Tn * HSn / 2);

    int tid = threadIdx.x;
    int lane = tid & 31, wid = tid >> 5;
    int wm2 = wid >> 1;
    int wn2 = wid & 1;
    int lg = lane >> 2, lq = lane & 3;

    float acc[2][4][4] = {};

    int ar = tid >> 1, ac8 = (tid & 1) * 2;
    int vr = tid >> 4, vc = tid & 15;

    uint32_t sa2b = smem_u32(sa2);
    uint32_t aal = sa2b + (uint32_t)(((wm2 * 32 + (lane & 15)) * AVW + (lane >> 4) * 4) * 4);

    int klim = row0 + 128;
    for (int k0 = 0; k0 < klim; k0 += 32) {
#pragma unroll
        for (int j = 0; j < 2; j++)
            *(uint4*)&sa2[ar * AVW + (ac8 + j) * 4] =
                *(const uint4*)(Am + (size_t)(row0 + ar) * Tn + k0 + (ac8 + j) * 8);
        *(uint4*)&sv[vr * VW + vc * 4] =
            *(const uint4*)(Vw + ((size_t)((k0 >> 1) + vr)) * HSn + vc * 4);
        __syncthreads();
#pragma unroll
        for (int ks = 0; ks < 2; ks++) {
            int kbw = ks * 8;
            uint32_t af[2][4], bf[4][2];
#pragma unroll
            for (int mi = 0; mi < 2; mi++)
                ldmat4(af[mi], aal + (uint32_t)((mi * 16 * AVW + kbw) * 4));
#pragma unroll
            for (int ni = 0; ni < 4; ni++) {
                int nc = wn2 * 32 + ni * 8 + lg;
                bf[ni][0] = sv[(kbw + lq) * VW + nc];
                bf[ni][1] = sv[(kbw + 4 + lq) * VW + nc];
            }
#pragma unroll
            for (int mi = 0; mi < 2; mi++)
#pragma unroll
                for (int ni = 0; ni < 4; ni++)
                    mma_fp16(acc[mi][ni], af[mi], bf[ni]);
        }
        __syncthreads();
    }

    int b = z / Hn, h = z % Hn;
#pragma unroll
    for (int mi = 0; mi < 2; mi++)
#pragma unroll
        for (int ni = 0; ni < 4; ni++)
#pragma unroll
            for (int hf = 0; hf < 2; hf++) {
                int t = row0 + wm2 * 32 + mi * 16 + lg + hf * 8;
                int d = wn2 * 32 + ni * 8 + lq * 2;
                size_t oi = ((size_t)b * Tn + t) * Cn + h * HSn + d;
                *(__half2*)(g_y + oi) =
                    __floats2half2_rn(acc[mi][ni][hf * 2 + 0],
                                      acc[mi][ni][hf * 2 + 1]);
            }
}

// ---------------- launch ----------------
extern "C" void kernel_launch(void* const* d_in, const int* in_sizes, int n_in,
                              void* d_out, int out_size) {
    const float* x         = (const float*)d_in[0];
    const float* ln1_g     = (const float*)d_in[1];
    const float* ln1_b     = (const float*)d_in[2];
    const float* Wq        = (const float*)d_in[3];
    const float* bq        = (const float*)d_in[4];
    const float* Wk        = (const float*)d_in[5];
    const float* bk        = (const float*)d_in[6];
    const float* Wv        = (const float*)d_in[7];
    const float* bv        = (const float*)d_in[8];
    const float* Wo        = (const float*)d_in[9];
    const float* bo        = (const float*)d_in[10];
    const float* time_w    = (const float*)d_in[11];
    const float* time_alpha= (const float*)d_in[12];
    const float* time_beta = (const float*)d_in[13];
    const float* time_gamma= (const float*)d_in[14];
    const float* Wmix      = (const float*)d_in[15];
    const float* ln2_g     = (const float*)d_in[16];
    const float* ln2_b     = (const float*)d_in[17];
    const float* Wgk       = (const float*)d_in[18];
    const float* bgk       = (const float*)d_in[19];
    const float* Wgv       = (const float*)d_in[20];
    const float* bgv       = (const float*)d_in[21];
    const float* Wgw       = (const float*)d_in[22];
    const float* bgw       = (const float*)d_in[23];

    __half *xs, *q, *k, *v, *gvb, *yb, *atth, *xmp;
    float *x1;
    uint32_t* wh;
    cudaGetSymbolAddress((void**)&xs,  g_xs);
    cudaGetSymbolAddress((void**)&q,   g_q);
    cudaGetSymbolAddress((void**)&k,   g_k);
    cudaGetSymbolAddress((void**)&v,   g_v);
    cudaGetSymbolAddress((void**)&yb,  g_y);
    cudaGetSymbolAddress((void**)&x1,  g_x1);
    cudaGetSymbolAddress((void**)&gvb, g_gv);
    cudaGetSymbolAddress((void**)&atth, g_att);
    cudaGetSymbolAddress((void**)&wh,  g_wh);
    cudaGetSymbolAddress((void**)&xmp, g_xm);
    float* part = (float*)atth;
    const __half* whh = (const __half*)wh;

    static bool attr_done = false;
    if (!attr_done) {
        cudaFuncSetAttribute(softmax_mix, cudaFuncAttributeMaxDynamicSharedMemorySize, SMIX_SMEM);
        cudaFuncSetAttribute(gemm_qkv,    cudaFuncAttributeMaxDynamicSharedMemorySize, GEMM_SMEMW * 4);
        cudaFuncSetAttribute(gemm_splitk, cudaFuncAttributeMaxDynamicSharedMemorySize, GEMM_SMEMW * 4);
        cudaFuncSetAttribute(gemm_ffn_dual, cudaFuncAttributeMaxDynamicSharedMemorySize, DUAL_SMEMW * 4);
        attr_done = true;
    }

    const int M = Bn * Tn;   // 2048
    dim3 tb(32, 8);

    // 0) weight conversion: transpose to [n][k] half
    W4 w4; w4.w[0] = Wq; w4.w[1] = Wk; w4.w[2] = Wv; w4.w[3] = Wo;
    convT_cc<<<dim3(32, 32, 4), tb>>>(w4);
    convT_cf<<<dim3(128, 32, 2), tb>>>(Wgk, Wgv);
    convT_gw<<<dim3(32, 128), tb>>>(Wgw);

    // 1) LN1 + time shift
    ln1_shift_kernel<<<Bn * Tn, 256>>>(x, ln1_g, ln1_b);

    // 2) QKV fused; rotary fused; v k-packed
    QKVArgs qa = {bq, bk, bv, q, k, v};
    gemm_qkv<<<dim3(Cn / 128, M / 128, 3), 256, GEMM_SMEMW * 4>>>(xs, qa);

    // 3) scores (triangular grid)
    scores_mma<<<dim3(36, Bn * Hn), 256>>>();

    // 4) softmax * w + head mix
    softmax_mix<<<dim3(Tn, Bn), 256, SMIX_SMEM>>>(time_w, time_alpha, time_beta, Wmix);

    // 5) y = att2 @ v
    av_mma<<<dim3(Tn / 128, Bn * Hn), 256>>>();

    // 6) out projection: split-K=2, fused finalize+LN2
    gemm_splitk<<<dim3(Cn / 128, M / 128, 2), 256, GEMM_SMEMW * 4>>>(
        yb, whh + HOFF_O, part, Cn, Cn);
    ln2_fused<<<Bn * Tn, 256>>>(part, bo, time_gamma, x, ln2_g, ln2_b);

    // 7) FFN up: dual GEMM
    gemm_ffn_dual<<<dim3(FFNn / 128, M / 128), 256, DUAL_SMEMW * 4>>>(
        xmp, whh + HOFF_GK, whh + HOFF_GV, bgk, bgv, gvb);

    // 8) FFN down: split-K=2 + finalize
    gemm_splitk<<<dim3(Cn / 128, M / 128, 2), 256, GEMM_SMEMW * 4>>>(
        gvb, whh + HOFF_GW, part, Cn, FFNn);
    fin_wgw<<<(M * Cn) / (256 * 4), 256>>>(part, bgw, x1, (float*)d_out);
}

// round 17
// speedup vs baseline: 1.0158x; 1.0158x over previous
#include <cuda_runtime.h>
#include <cuda_fp16.h>
#include <cstdint>
#include <math.h>

#define Bn   2
#define Tn   1024
#define Cn   1024
#define Hn   16
#define HSn  64
#define TTn  1024
#define FFNn 4096
#define EPSn 1e-6f

// ---------------- scratch ----------------
__device__ __half g_xs [Bn*Tn*Cn];
__device__ __half g_q  [Bn*Tn*Cn];
__device__ __half g_k  [Bn*Tn*Cn];
__device__ __half g_v  [Bn*Tn*Cn];          // k-pair packed per (b,h)
__device__ __half g_att [Bn*Hn*Tn*Tn];      // aliased as fp32 split-K partials
__device__ __half g_att2[Bn*Hn*Tn*Tn];
__device__ __half g_y  [Bn*Tn*Cn];
__device__ float  g_x1 [Bn*Tn*Cn];
__device__ __half g_xm [Bn*Tn*Cn];
__device__ __half g_gv [Bn*Tn*FFNn];
__device__ uint32_t g_wh[8*1024*1024];      // weights as half [n][k], 32MB

// half-element offsets into g_wh
#define HOFF_Q   0u
#define HOFF_K   (1u<<20)
#define HOFF_V   (2u<<20)
#define HOFF_O   (3u<<20)
#define HOFF_GK  (4u<<20)
#define HOFF_GV  (8u<<20)
#define HOFF_GW  (12u<<20)

// ---------------- helpers ----------------
__device__ __forceinline__ void mma_fp16(float* d, const uint32_t* a, const uint32_t* b) {
    asm volatile(
        "mma.sync.aligned.m16n8k16.row.col.f32.f16.f16.f32 "
        "{%0,%1,%2,%3}, {%4,%5,%6,%7}, {%8,%9}, {%0,%1,%2,%3};"
        : "+f"(d[0]), "+f"(d[1]), "+f"(d[2]), "+f"(d[3])
        : "r"(a[0]), "r"(a[1]), "r"(a[2]), "r"(a[3]), "r"(b[0]), "r"(b[1]));
}
__device__ __forceinline__ void ldmat4(uint32_t* r, uint32_t addr) {
    asm volatile(
        "ldmatrix.sync.aligned.m8n8.x4.shared.b16 {%0,%1,%2,%3}, [%4];"
        : "=r"(r[0]), "=r"(r[1]), "=r"(r[2]), "=r"(r[3]) : "r"(addr));
}
__device__ __forceinline__ uint32_t smem_u32(const void* p) {
    uint32_t a;
    asm("{ .reg .u64 t; cvta.to.shared.u64 t, %1; cvt.u32.u64 %0, t; }"
        : "=r"(a) : "l"(p));
    return a;
}
__device__ __forceinline__ void cp16(uint32_t dst, const void* src) {
    asm volatile("cp.async.ca.shared.global [%0], [%1], 16;" :: "r"(dst), "l"(src));
}
__device__ __forceinline__ void cp_commit() {
    asm volatile("cp.async.commit_group;" ::: "memory");
}
template<int N> __device__ __forceinline__ void cp_wait() {
    asm volatile("cp.async.wait_group %0;" :: "n"(N) : "memory");
}

// ---------------- weight conversion: W[k][n] f32 -> Wt[n][k] half -----------
struct W4 { const float* w[4]; };

__device__ __forceinline__ void transpose_tile(const float* __restrict__ W,
                                               __half* __restrict__ dst,
                                               int K, int N) {
    __shared__ float tile[32][33];
    int bx = blockIdx.x * 32;  // n
    int by = blockIdx.y * 32;  // k
    int tx = threadIdx.x, ty = threadIdx.y;
#pragma unroll
    for (int i = 0; i < 32; i += 8)
        tile[ty + i][tx] = W[(size_t)(by + ty + i) * N + bx + tx];
    __syncthreads();
#pragma unroll
    for (int i = 0; i < 32; i += 8)
        dst[(size_t)(bx + ty + i) * K + by + tx] = __float2half(tile[tx][ty + i]);
}

__global__ void convT_cc(W4 ws) {
    transpose_tile(ws.w[blockIdx.z],
                   (__half*)g_wh + (size_t)blockIdx.z * (1u << 20), Cn, Cn);
}
__global__ void convT_cf(const float* W0, const float* W1) {
    transpose_tile(blockIdx.z ? W1 : W0,
                   (__half*)g_wh + HOFF_GK + (size_t)blockIdx.z * (4u << 20),
                   Cn, FFNn);
}
__global__ void convT_gw(const float* W) {
    transpose_tile(W, (__half*)g_wh + HOFF_GW, FFNn, Cn);
}

// ---------------- fast row reduce ----------------
__device__ __forceinline__ void row_stats(float4 v4, float& mean, float& rstd,
                                          float* red) {
    int tid = threadIdx.x, lane = tid & 31, w = tid >> 5;
    float s  = v4.x + v4.y + v4.z + v4.w;
    float s2 = v4.x*v4.x + v4.y*v4.y + v4.z*v4.z + v4.w*v4.w;
#pragma unroll
    for (int o = 16; o; o >>= 1) {
        s  += __shfl_xor_sync(0xFFFFFFFFu, s,  o);
        s2 += __shfl_xor_sync(0xFFFFFFFFu, s2, o);
    }
    if (lane == 0) { red[w] = s; red[8 + w] = s2; }
    __syncthreads();
    if (tid == 0) {
        float a = 0.f, b2 = 0.f;
#pragma unroll
        for (int i = 0; i < 8; i++) { a += red[i]; b2 += red[8 + i]; }
        red[16] = a; red[17] = b2;
    }
    __syncthreads();
    mean = red[16] / Cn;
    rstd = rsqrtf(red[17] / Cn - mean * mean + EPSn);
}

// ---------------- LN1 + time_shift_half ----------------
__global__ __launch_bounds__(256)
void ln1_shift_kernel(const float* __restrict__ x,
                      const float* __restrict__ g,
                      const float* __restrict__ b) {
    __shared__ float red[18];
    int bt = blockIdx.x;
    int bb = bt >> 10, t = bt & (Tn - 1);
    int c = threadIdx.x * 4;
    float4 v4 = *(const float4*)(x + (size_t)bt * Cn + c);
    float mean, rstd;
    row_stats(v4, mean, rstd, red);
    float4 g4 = *(const float4*)(g + c);
    float4 b4 = *(const float4*)(b + c);
    __half2 h01 = __floats2half2_rn((v4.x - mean) * rstd * g4.x + b4.x,
                                    (v4.y - mean) * rstd * g4.y + b4.y);
    __half2 h23 = __floats2half2_rn((v4.z - mean) * rstd * g4.z + b4.z,
                                    (v4.w - mean) * rstd * g4.w + b4.w);
    uint2 pk; pk.x = *(uint32_t*)&h01; pk.y = *(uint32_t*)&h23;
    if (c < Cn / 2) {
        if (t + 1 < Tn)
            *(uint2*)(g_xs + ((size_t)bb * Tn + t + 1) * Cn + c) = pk;
        if (t == 0)
            *(uint2*)(g_xs + (size_t)bb * Tn * Cn + c) = make_uint2(0, 0);
    } else {
        *(uint2*)(g_xs + (size_t)bt * Cn + c) = pk;
    }
}

// ---------------- fused fin_wo + LN2 ----------------
__global__ __launch_bounds__(256)
void ln2_fused(const float* __restrict__ P, const float* __restrict__ bo,
               const float* __restrict__ gamma, const float* __restrict__ x,
               const float* __restrict__ g, const float* __restrict__ b) {
    __shared__ float red[18];
    int bt = blockIdx.x;
    int t = bt & (Tn - 1);
    int c = threadIdx.x * 4;
    const size_t half = (size_t)(Bn * Tn) * Cn;
    size_t i = (size_t)bt * Cn + c;
    float4 a4 = *(const float4*)(P + i);
    float4 p4 = *(const float4*)(P + half + i);
    float4 x4 = *(const float4*)(x + i);
    float4 bo4 = *(const float4*)(bo + c);
    float gm = gamma[t];
    float4 v4;
    v4.x = (a4.x + p4.x + bo4.x) * gm + x4.x;
    v4.y = (a4.y + p4.y + bo4.y) * gm + x4.y;
    v4.z = (a4.z + p4.z + bo4.z) * gm + x4.z;
    v4.w = (a4.w + p4.w + bo4.w) * gm + x4.w;
    *(float4*)(g_x1 + i) = v4;
    float mean, rstd;
    row_stats(v4, mean, rstd, red);
    float4 g4 = *(const float4*)(g + c);
    float4 b4 = *(const float4*)(b + c);
    __half2 h01 = __floats2half2_rn((v4.x - mean) * rstd * g4.x + b4.x,
                                    (v4.y - mean) * rstd * g4.y + b4.y);
    __half2 h23 = __floats2half2_rn((v4.z - mean) * rstd * g4.z + b4.z,
                                    (v4.w - mean) * rstd * g4.w + b4.w);
    uint2 pk; pk.x = *(uint32_t*)&h01; pk.y = *(uint32_t*)&h23;
    *(uint2*)(g_xm + i) = pk;
}

// ======== fp16 GEMM core (128x128, 8 warps, K-chunk 64, 2-stage, ldmatrix) ==
#define EPI_NONE  0
#define EPI_QKV   1

#define AW 36
#define BW2 36
#define ABUFW (128*AW)
#define BBUFW2 (128*BW2)
#define GEMM_SMEMW (2*(ABUFW+BBUFW2))

template<int MODE>
__device__ __forceinline__ void gemm_body(
    uint32_t* usm,
    const __half* __restrict__ A, const __half* __restrict__ Bh,
    const float* __restrict__ bias, void* __restrict__ Cv,
    int N, int Kfull, int koff, int kspan,
    int row0, int col0, int qkvmode)
{
    uint32_t sb = smem_u32(usm);
    int tid = threadIdx.x;
    int lane = tid & 31, wid = tid >> 5;
    int wm = wid >> 2, wn = wid & 3;
    int lg = lane >> 2, lq = lane & 3;

    float acc[4][4][4] = {};

    int aw = (tid & 1) * 16;
    const __half* Ab = A + (size_t)(row0 + (tid >> 1)) * Kfull + koff + aw * 2;
    const __half* Bb = Bh + (size_t)(col0 + (tid >> 1)) * Kfull + koff + aw * 2;
    uint32_t adst0 = sb + (uint32_t)(((tid >> 1) * AW + aw) * 4);
    uint32_t bdst0 = sb + (uint32_t)((2 * ABUFW + (tid >> 1) * BW2 + aw) * 4);

    uint32_t albase = sb + (uint32_t)(((wm * 64 + (lane & 15)) * AW + (lane >> 4) * 4) * 4);
    uint32_t blbase = sb + (uint32_t)((2 * ABUFW + (wn * 32 + (lane & 15)) * BW2 + (lane >> 4) * 4) * 4);

    const int nch = kspan >> 6;

#define GISS(ci) do { \
    int _p = (ci) & 1; int _k0 = (ci) << 6; \
    uint32_t _ad = adst0 + _p * ABUFW * 4; \
    const __half* _a = Ab + _k0; \
    cp16(_ad,      _a);      cp16(_ad + 16, _a + 8); \
    cp16(_ad + 32, _a + 16); cp16(_ad + 48, _a + 24); \
    uint32_t _bd = bdst0 + _p * BBUFW2 * 4; \
    const __half* _b = Bb + _k0; \
    cp16(_bd,      _b);      cp16(_bd + 16, _b + 8); \
    cp16(_bd + 32, _b + 16); cp16(_bd + 48, _b + 24); \
} while (0)

    GISS(0); cp_commit();

    for (int ci = 0; ci < nch; ci++) {
        cp_wait<0>();
        __syncthreads();
        if (ci + 1 < nch) { GISS(ci + 1); cp_commit(); }

        uint32_t al = albase + (ci & 1) * (ABUFW * 4);
        uint32_t bl = blbase + (ci & 1) * (BBUFW2 * 4);
#pragma unroll
        for (int ks = 0; ks < 4; ks++) {
            int kbw = ks * 8;
            uint32_t af[4][4], bp[2][4];
#pragma unroll
            for (int mi = 0; mi < 4; mi++)
                ldmat4(af[mi], al + (uint32_t)((mi * 16 * AW + kbw) * 4));
#pragma unroll
            for (int j = 0; j < 2; j++)
                ldmat4(bp[j], bl + (uint32_t)((j * 16 * BW2 + kbw) * 4));
#pragma unroll
            for (int mi = 0; mi < 4; mi++)
#pragma unroll
                for (int ni = 0; ni < 4; ni++) {
                    uint32_t bf[2] = { bp[ni >> 1][ni & 1], bp[ni >> 1][2 + (ni & 1)] };
                    mma_fp16(acc[mi][ni], af[mi], bf);
                }
        }
        __syncthreads();
    }
#undef GISS

    if (MODE == EPI_QKV) {
        __half* out = (__half*)Cv;
#pragma unroll
        for (int mi = 0; mi < 4; mi++) {
#pragma unroll
            for (int hf = 0; hf < 2; hf++) {
                int r = row0 + wm * 64 + mi * 16 + lg + hf * 8;
                int bI = r >> 10, t = r & (Tn - 1);
                float v[4][2];
#pragma unroll
                for (int ni = 0; ni < 4; ni++) {
                    int c = col0 + wn * 32 + ni * 8 + lq * 2;
                    v[ni][0] = acc[mi][ni][hf * 2 + 0] + bias[c];
                    v[ni][1] = acc[mi][ni][hf * 2 + 1] + bias[c + 1];
                }
                if (qkvmode == 0 && !(wn & 1)) {
#pragma unroll
                    for (int ni = 0; ni < 2; ni++) {
                        int d0 = ni * 8 + lq * 2;
#pragma unroll
                        for (int j = 0; j < 2; j++) {
                            float ang = (float)t * exp2f(-0.625f * (float)(d0 + j));
                            float sv, cv;
                            sincosf(ang, &sv, &cv);
                            float a = v[ni][j], b2 = v[ni + 2][j];
                            v[ni][j]     = a * cv - b2 * sv;
                            v[ni + 2][j] = b2 * cv + a * sv;
                        }
                    }
                }
#pragma unroll
                for (int ni = 0; ni < 4; ni++) {
                    int c = col0 + wn * 32 + ni * 8 + lq * 2;
                    int h = c >> 6, d = c & 63;
                    size_t base = ((size_t)bI * Hn + h) * ((size_t)Tn * HSn);
                    __half2 h2 = __floats2half2_rn(v[ni][0], v[ni][1]);
                    if (qkvmode != 2) {
                        *(__half2*)(out + base + (size_t)t * HSn + d) = h2;
                    } else {
                        size_t w = base + ((size_t)(t >> 1) * HSn + d) * 2 + (t & 1);
                        out[w]     = __low2half(h2);
                        out[w + 2] = __high2half(h2);
                    }
                }
            }
        }
    } else {
        float* out = (float*)Cv;
#pragma unroll
        for (int mi = 0; mi < 4; mi++)
#pragma unroll
            for (int ni = 0; ni < 4; ni++)
#pragma unroll
                for (int hf = 0; hf < 2; hf++) {
                    int r = row0 + wm * 64 + mi * 16 + lg + hf * 8;
                    int c = col0 + wn * 32 + ni * 8 + lq * 2;
                    size_t oi = (size_t)r * N + c;
                    out[oi]     = acc[mi][ni][hf * 2 + 0];
                    out[oi + 1] = acc[mi][ni][hf * 2 + 1];
                }
    }
}

struct QKVArgs {
    const float *b0, *b1, *b2;
    __half *q, *k, *v;
};

__global__ __launch_bounds__(256, 2)
void gemm_qkv(const __half* __restrict__ A, QKVArgs a) {
    extern __shared__ uint32_t usm[];
    int z = blockIdx.z;
    const __half* Bh = (const __half*)g_wh + (size_t)z * (1u << 20);
    const float* bias = (z == 0) ? a.b0 : (z == 1) ? a.b1 : a.b2;
    __half* out = (z == 0) ? a.q : (z == 1) ? a.k : a.v;
    gemm_body<EPI_QKV>(usm, A, Bh, bias, out, Cn, Cn, 0, Cn,
                       blockIdx.y * 128, blockIdx.x * 128, (z == 2) ? 2 : 0);
}

__global__ __launch_bounds__(256, 2)
void gemm_splitk(const __half* __restrict__ A, const __half* __restrict__ Bh,
                 float* __restrict__ P, int N, int Kfull) {
    extern __shared__ uint32_t usm[];
    int z = blockIdx.z;
    int kh = Kfull >> 1;
    float* out = P + (size_t)z * (Bn * Tn) * Cn;
    gemm_body<EPI_NONE>(usm, A, Bh, nullptr, out, N, Kfull, z * kh, kh,
                        blockIdx.y * 128, blockIdx.x * 128, -1);
}

// ================= dual FFN-up GEMM (K-chunk 64, 2-stage, ldmatrix) =========
#define DUAL_SMEMW (2*ABUFW + 4*BBUFW2)

__global__ __launch_bounds__(256)
void gemm_ffn_dual(const __half* __restrict__ A,
                   const __half* __restrict__ B1h,
                   const __half* __restrict__ B2h,
                   const float* __restrict__ bias1,
                   const float* __restrict__ bias2,
                   __half* __restrict__ C) {
    extern __shared__ uint32_t usm[];
    const int K = Cn;
    uint32_t sb = smem_u32(usm);
    int tid = threadIdx.x;
    int lane = tid & 31, wid = tid >> 5;
    int wm = wid >> 2, wn = wid & 3;
    int lg = lane >> 2, lq = lane & 3;
    int row0 = blockIdx.y * 128, col0 = blockIdx.x * 128;

    float acc1[4][4][4] = {};
    float acc2[4][4][4] = {};

    int aw = (tid & 1) * 16;
    const __half* Ab  = A   + (size_t)(row0 + (tid >> 1)) * K + aw * 2;
    const __half* B1b = B1h + (size_t)(col0 + (tid >> 1)) * K + aw * 2;
    const __half* B2b = B2h + (size_t)(col0 + (tid >> 1)) * K + aw * 2;
    uint32_t adst0  = sb + (uint32_t)(((tid >> 1) * AW + aw) * 4);
    uint32_t b1dst0 = sb + (uint32_t)((2 * ABUFW + (tid >> 1) * BW2 + aw) * 4);
    uint32_t b2dst0 = b1dst0 + 2 * BBUFW2 * 4;

    uint32_t albase  = sb + (uint32_t)(((wm * 64 + (lane & 15)) * AW + (lane >> 4) * 4) * 4);
    uint32_t b1lbase = sb + (uint32_t)((2 * ABUFW + (wn * 32 + (lane & 15)) * BW2 + (lane >> 4) * 4) * 4);
    uint32_t b2lbase = b1lbase + 2 * BBUFW2 * 4;

    const int nch = K >> 6;

#define DISS(ci) do { \
    int _p = (ci) & 1; int _k0 = (ci) << 6; \
    uint32_t _ad = adst0 + _p * ABUFW * 4; \
    const __half* _a = Ab + _k0; \
    cp16(_ad,      _a);      cp16(_ad + 16, _a + 8); \
    cp16(_ad + 32, _a + 16); cp16(_ad + 48, _a + 24); \
    uint32_t _b1d = b1dst0 + _p * BBUFW2 * 4; \
    const __half* _b1 = B1b + _k0; \
    cp16(_b1d,      _b1);      cp16(_b1d + 16, _b1 + 8); \
    cp16(_b1d + 32, _b1 + 16); cp16(_b1d + 48, _b1 + 24); \
    uint32_t _b2d = b2dst0 + _p * BBUFW2 * 4; \
    const __half* _b2 = B2b + _k0; \
    cp16(_b2d,      _b2);      cp16(_b2d + 16, _b2 + 8); \
    cp16(_b2d + 32, _b2 + 16); cp16(_b2d + 48, _b2 + 24); \
} while (0)

    DISS(0); cp_commit();

    for (int ci = 0; ci < nch; ci++) {
        cp_wait<0>();
        __syncthreads();
        if (ci + 1 < nch) { DISS(ci + 1); cp_commit(); }

        uint32_t al  = albase  + (ci & 1) * (ABUFW * 4);
        uint32_t b1l = b1lbase + (ci & 1) * (BBUFW2 * 4);
        uint32_t b2l = b2lbase + (ci & 1) * (BBUFW2 * 4);
#pragma unroll
        for (int ks = 0; ks < 4; ks++) {
            int kbw = ks * 8;
            uint32_t af[4][4], bp1[2][4], bp2[2][4];
#pragma unroll
            for (int mi = 0; mi < 4; mi++)
                ldmat4(af[mi], al + (uint32_t)((mi * 16 * AW + kbw) * 4));
#pragma unroll
            for (int j = 0; j < 2; j++) {
                ldmat4(bp1[j], b1l + (uint32_t)((j * 16 * BW2 + kbw) * 4));
                ldmat4(bp2[j], b2l + (uint32_t)((j * 16 * BW2 + kbw) * 4));
            }
#pragma unroll
            for (int mi = 0; mi < 4; mi++)
#pragma unroll
                for (int ni = 0; ni < 4; ni++) {
                    uint32_t bf1[2] = { bp1[ni >> 1][ni & 1], bp1[ni >> 1][2 + (ni & 1)] };
                    uint32_t bf2[2] = { bp2[ni >> 1][ni & 1], bp2[ni >> 1][2 + (ni & 1)] };
                    mma_fp16(acc1[mi][ni], af[mi], bf1);
                    mma_fp16(acc2[mi][ni], af[mi], bf2);
                }
        }
        __syncthreads();
    }
#undef DISS

#pragma unroll
    for (int mi = 0; mi < 4; mi++) {
#pragma unroll
        for (int ni = 0; ni < 4; ni++) {
#pragma unroll
            for (int hf = 0; hf < 2; hf++) {
                int r = row0 + wm * 64 + mi * 16 + lg + hf * 8;
                int c = col0 + wn * 32 + ni * 8 + lq * 2;
                float k0 = acc1[mi][ni][hf * 2 + 0] + bias1[c];
                float k1 = acc1[mi][ni][hf * 2 + 1] + bias1[c + 1];
                float m0 = acc2[mi][ni][hf * 2 + 0] + bias2[c];
                float m1 = acc2[mi][ni][hf * 2 + 1] + bias2[c + 1];
                float gl0 = 0.5f * k0 * (1.f + erff(k0 * 0.70710678118654752f));
                float gl1 = 0.5f * k1 * (1.f + erff(k1 * 0.70710678118654752f));
                *(__half2*)(C + (size_t)r * FFNn + c) =
                    __floats2half2_rn(gl0 * m0, gl1 * m1);
            }
        }
    }
}

// finalize Wgw
__global__ void fin_wgw(const float* __restrict__ P, const float* __restrict__ bgw,
                        const float* __restrict__ x1, float* __restrict__ out) {
    size_t i = ((size_t)blockIdx.x * 256 + threadIdx.x) * 4;
    const size_t half = (size_t)(Bn * Tn) * Cn;
    float4 a = *(const float4*)(P + i);
    float4 b = *(const float4*)(P + half + i);
    float4 r = *(const float4*)(x1 + i);
    int c = (int)(i & (Cn - 1));
    float4 o;
    o.x = a.x + b.x + bgw[c]     + r.x;
    o.y = a.y + b.y + bgw[c + 1] + r.y;
    o.z = a.z + b.z + bgw[c + 2] + r.z;
    o.w = a.w + b.w + bgw[c + 3] + r.w;
    *(float4*)(out + i) = o;
}

// ---------------- scores via fp16 mma (NT, triangular grid, ldmatrix) ------
#define SW 36
__global__ __launch_bounds__(256, 2)
void scores_mma() {
    int i = blockIdx.x;
    int tt = (int)((sqrtf(8.f * (float)i + 1.f) - 1.f) * 0.5f);
    while ((tt + 1) * (tt + 2) / 2 <= i) tt++;
    while (tt * (tt + 1) / 2 > i) tt--;
    int ut = i - tt * (tt + 1) / 2;
    int z = blockIdx.y;
    int row0 = tt * 128, col0 = ut * 128;
    const __half* q = g_q + (size_t)z * Tn * HSn;
    const __half* k = g_k + (size_t)z * Tn * HSn;

    __shared__ uint32_t sq[128 * SW];
    __shared__ uint32_t sk[128 * SW];

    int tid = threadIdx.x;
    int lane = tid & 31, wid = tid >> 5;
    int wm = wid >> 2, wn = wid & 3;

#pragma unroll
    for (int it = 0; it < 4; it++) {
        int id = it * 256 + tid;
        int row = id >> 3, c8 = id & 7;
        *(uint4*)&sq[row * SW + c8 * 4] =
            *(const uint4*)(q + (size_t)(row0 + row) * HSn + c8 * 8);
        *(uint4*)&sk[row * SW + c8 * 4] =
            *(const uint4*)(k + (size_t)(col0 + row) * HSn + c8 * 8);
    }
    __syncthreads();

    uint32_t sqb = smem_u32(sq);
    uint32_t skb = smem_u32(sk);
    uint32_t qal = sqb + (uint32_t)(((wm * 64 + (lane & 15)) * SW + (lane >> 4) * 4) * 4);
    uint32_t kal = skb + (uint32_t)(((wn * 32 + (lane & 15)) * SW + (lane >> 4) * 4) * 4);

    float acc[4][4][4] = {};
#pragma unroll
    for (int ks = 0; ks < 4; ks++) {
        int kbw = ks * 8;
        uint32_t af[4][4], bp[2][4];
#pragma unroll
        for (int mi = 0; mi < 4; mi++)
            ldmat4(af[mi], qal + (uint32_t)((mi * 16 * SW + kbw) * 4));
#pragma unroll
        for (int j = 0; j < 2; j++)
            ldmat4(bp[j], kal + (uint32_t)((j * 16 * SW + kbw) * 4));
#pragma unroll
        for (int mi = 0; mi < 4; mi++)
#pragma unroll
            for (int ni = 0; ni < 4; ni++) {
                uint32_t bf[2] = { bp[ni >> 1][ni & 1], bp[ni >> 1][2 + (ni & 1)] };
                mma_fp16(acc[mi][ni], af[mi], bf);
            }
    }

    int lg = lane >> 2, lq = lane & 3;
    __half* out = g_att + (size_t)z * Tn * Tn;
#pragma unroll
    for (int mi = 0; mi < 4; mi++)
#pragma unroll
        for (int ni = 0; ni < 4; ni++)
#pragma unroll
            for (int hf = 0; hf < 2; hf++) {
                int r = row0 + wm * 64 + mi * 16 + lg + hf * 8;
                int c = col0 + wn * 32 + ni * 8 + lq * 2;
                *(__half2*)(out + (size_t)r * Tn + c) =
                    __floats2half2_rn(acc[mi][ni][hf * 2 + 0] * 0.125f,
                                      acc[mi][ni][hf * 2 + 1] * 0.125f);
            }
}

// ---------------- fused softmax (causal) * w + head-mix ----------------
#define SMIX_SMEM ((Hn*Tn + 256) * 4)
__global__ __launch_bounds__(256)
void softmax_mix(const float* __restrict__ time_w,
                 const float* __restrict__ alpha,
                 const float* __restrict__ beta,
                 const float* __restrict__ Wmix) {
    extern __shared__ float sm[];
    float* p  = sm;
    float* wm = sm + Hn * Tn;
    int t = blockIdx.x, b = blockIdx.y;
    int tid = threadIdx.x, lane = tid & 31, w = tid >> 5;
    if (tid < 256) wm[tid] = Wmix[tid];
    int len = t + 1;

#pragma unroll
    for (int hh = 0; hh < 2; hh++) {
        int h = w * 2 + hh;
        const __half* src = g_att + (((size_t)b * Hn + h) * Tn + t) * Tn;
        float* ph = p + h * Tn;
        float mx = -1e30f;
        for (int u = lane; u < len; u += 32) {
            float v = __half2float(src[u]); ph[u] = v; mx = fmaxf(mx, v);
        }
#pragma unroll
        for (int o = 16; o; o >>= 1) mx = fmaxf(mx, __shfl_xor_sync(0xFFFFFFFFu, mx, o));
        float sum = 0.f;
        for (int u = lane; u < len; u += 32) {
            float e = expf(ph[u] - mx); ph[u] = e; sum += e;
        }
#pragma unroll
        for (int o = 16; o; o >>= 1) sum += __shfl_xor_sync(0xFFFFFFFFu, sum, o);
        float inv = 1.f / sum;
        float bt = beta[h * Tn + t];
        const float* twr = time_w + h * TTn + (TTn - 1 - t);
        const float* alr = alpha + h * Tn;
        for (int u = lane; u < len; u += 32)
            ph[u] *= inv * twr[u] * alr[u] * bt;
    }
    __syncthreads();

    int zend = (t / 128) * 128 + 128;
    const size_t stride = (size_t)Tn * Tn;
    for (int u = tid; u < zend; u += 256) {
        size_t obase = (((size_t)b * Hn) * Tn + t) * Tn + u;
        if (u < len) {
            float vals[Hn];
#pragma unroll
            for (int j = 0; j < Hn; j++) vals[j] = p[j * Tn + u];
#pragma unroll
            for (int i = 0; i < Hn; i++) {
                float s = 0.f;
#pragma unroll
                for (int j = 0; j < Hn; j++) s += wm[i * Hn + j] * vals[j];
                g_att2[obase + i * stride] = __float2half(s);
            }
        } else {
#pragma unroll
            for (int i = 0; i < Hn; i++)
                g_att2[obase + i * stride] = __float2half(0.f);
        }
    }
}

// ---------------- y = att2 @ v via fp16 mma (ldmatrix A) --------------------
#define AVW 20
#define VW 72
__global__ __launch_bounds__(256, 2)
void av_mma() {
    __shared__ uint32_t sa2[128 * AVW];
    __shared__ uint32_t sv [16 * VW];
    int tt = blockIdx.x;
    int z  = blockIdx.y;
    int row0 = tt * 128;
    const __half* Am = g_att2 + (size_t)z * Tn * Tn;
    const uint32_t* Vw = (const uint32_t*)g_v + (size_t)z * (Tn * HSn / 2);

    int tid = threadIdx.x;
    int lane = tid & 31, wid = tid >> 5;
    int wm2 = wid >> 1;
    int wn2 = wid & 1;
    int lg = lane >> 2, lq = lane & 3;

    float acc[2][4][4] = {};

    int ar = tid >> 1, ac8 = (tid & 1) * 2;
    int vr = tid >> 4, vc = tid & 15;

    uint32_t sa2b = smem_u32(sa2);
    uint32_t aal = sa2b + (uint32_t)(((wm2 * 32 + (lane & 15)) * AVW + (lane >> 4) * 4) * 4);

    int klim = row0 + 128;
    for (int k0 = 0; k0 < klim; k0 += 32) {
#pragma unroll
        for (int j = 0; j < 2; j++)
            *(uint4*)&sa2[ar * AVW + (ac8 + j) * 4] =
                *(const uint4*)(Am + (size_t)(row0 + ar) * Tn + k0 + (ac8 + j) * 8);
        *(uint4*)&sv[vr * VW + vc * 4] =
            *(const uint4*)(Vw + ((size_t)((k0 >> 1) + vr)) * HSn + vc * 4);
        __syncthreads();
#pragma unroll
        for (int ks = 0; ks < 2; ks++) {
            int kbw = ks * 8;
            uint32_t af[2][4], bf[4][2];
#pragma unroll
            for (int mi = 0; mi < 2; mi++)
                ldmat4(af[mi], aal + (uint32_t)((mi * 16 * AVW + kbw) * 4));
#pragma unroll
            for (int ni = 0; ni < 4; ni++) {
                int nc = wn2 * 32 + ni * 8 + lg;
                bf[ni][0] = sv[(kbw + lq) * VW + nc];
                bf[ni][1] = sv[(kbw + 4 + lq) * VW + nc];
            }
#pragma unroll
            for (int mi = 0; mi < 2; mi++)
#pragma unroll
                for (int ni = 0; ni < 4; ni++)
                    mma_fp16(acc[mi][ni], af[mi], bf[ni]);
        }
        __syncthreads();
    }

    int b = z / Hn, h = z % Hn;
#pragma unroll
    for (int mi = 0; mi < 2; mi++)
#pragma unroll
        for (int ni = 0; ni < 4; ni++)
#pragma unroll
            for (int hf = 0; hf < 2; hf++) {
                int t = row0 + wm2 * 32 + mi * 16 + lg + hf * 8;
                int d = wn2 * 32 + ni * 8 + lq * 2;
                size_t oi = ((size_t)b * Tn + t) * Cn + h * HSn + d;
                *(__half2*)(g_y + oi) =
                    __floats2half2_rn(acc[mi][ni][hf * 2 + 0],
                                      acc[mi][ni][hf * 2 + 1]);
            }
}

// ---------------- launch ----------------
extern "C" void kernel_launch(void* const* d_in, const int* in_sizes, int n_in,
                              void* d_out, int out_size) {
    const float* x         = (const float*)d_in[0];
    const float* ln1_g     = (const float*)d_in[1];
    const float* ln1_b     = (const float*)d_in[2];
    const float* Wq        = (const float*)d_in[3];
    const float* bq        = (const float*)d_in[4];
    const float* Wk        = (const float*)d_in[5];
    const float* bk        = (const float*)d_in[6];
    const float* Wv        = (const float*)d_in[7];
    const float* bv        = (const float*)d_in[8];
    const float* Wo        = (const float*)d_in[9];
    const float* bo        = (const float*)d_in[10];
    const float* time_w    = (const float*)d_in[11];
    const float* time_alpha= (const float*)d_in[12];
    const float* time_beta = (const float*)d_in[13];
    const float* time_gamma= (const float*)d_in[14];
    const float* Wmix      = (const float*)d_in[15];
    const float* ln2_g     = (const float*)d_in[16];
    const float* ln2_b     = (const float*)d_in[17];
    const float* Wgk       = (const float*)d_in[18];
    const float* bgk       = (const float*)d_in[19];
    const float* Wgv       = (const float*)d_in[20];
    const float* bgv       = (const float*)d_in[21];
    const float* Wgw       = (const float*)d_in[22];
    const float* bgw       = (const float*)d_in[23];

    __half *xs, *q, *k, *v, *gvb, *yb, *atth, *xmp;
    float *x1;
    uint32_t* wh;
    cudaGetSymbolAddress((void**)&xs,  g_xs);
    cudaGetSymbolAddress((void**)&q,   g_q);
    cudaGetSymbolAddress((void**)&k,   g_k);
    cudaGetSymbolAddress((void**)&v,   g_v);
    cudaGetSymbolAddress((void**)&yb,  g_y);
    cudaGetSymbolAddress((void**)&x1,  g_x1);
    cudaGetSymbolAddress((void**)&gvb, g_gv);
    cudaGetSymbolAddress((void**)&atth, g_att);
    cudaGetSymbolAddress((void**)&wh,  g_wh);
    cudaGetSymbolAddress((void**)&xmp, g_xm);
    float* part = (float*)atth;
    const __half* whh = (const __half*)wh;

    static bool attr_done = false;
    static cudaStream_t s2 = nullptr;
    static cudaEvent_t evF = nullptr, evCC = nullptr, evW2 = nullptr;
    if (!attr_done) {
        cudaFuncSetAttribute(softmax_mix, cudaFuncAttributeMaxDynamicSharedMemorySize, SMIX_SMEM);
        cudaFuncSetAttribute(gemm_qkv,    cudaFuncAttributeMaxDynamicSharedMemorySize, GEMM_SMEMW * 4);
        cudaFuncSetAttribute(gemm_splitk, cudaFuncAttributeMaxDynamicSharedMemorySize, GEMM_SMEMW * 4);
        cudaFuncSetAttribute(gemm_ffn_dual, cudaFuncAttributeMaxDynamicSharedMemorySize, DUAL_SMEMW * 4);
        cudaStreamCreateWithFlags(&s2, cudaStreamNonBlocking);
        cudaEventCreateWithFlags(&evF,  cudaEventDisableTiming);
        cudaEventCreateWithFlags(&evCC, cudaEventDisableTiming);
        cudaEventCreateWithFlags(&evW2, cudaEventDisableTiming);
        attr_done = true;
    }

    const int M = Bn * Tn;   // 2048
    dim3 tb(32, 8);

    // fork: weight conversions on side stream s2
    cudaEventRecord(evF, 0);
    cudaStreamWaitEvent(s2, evF, 0);
    W4 w4; w4.w[0] = Wq; w4.w[1] = Wk; w4.w[2] = Wv; w4.w[3] = Wo;
    convT_cc<<<dim3(32, 32, 4), tb, 0, s2>>>(w4);
    cudaEventRecord(evCC, s2);
    convT_cf<<<dim3(128, 32, 2), tb, 0, s2>>>(Wgk, Wgv);
    convT_gw<<<dim3(32, 128), tb, 0, s2>>>(Wgw);
    cudaEventRecord(evW2, s2);

    // main chain (default stream): LN1 overlaps convT_cc
    ln1_shift_kernel<<<Bn * Tn, 256>>>(x, ln1_g, ln1_b);

    // join 1: qkv needs convT_cc
    cudaStreamWaitEvent(0, evCC, 0);
    QKVArgs qa = {bq, bk, bv, q, k, v};
    gemm_qkv<<<dim3(Cn / 128, M / 128, 3), 256, GEMM_SMEMW * 4>>>(xs, qa);

    // attention chain (overlaps convT_cf / convT_gw on s2)
    scores_mma<<<dim3(36, Bn * Hn), 256>>>();
    softmax_mix<<<dim3(Tn, Bn), 256, SMIX_SMEM>>>(time_w, time_alpha, time_beta, Wmix);
    av_mma<<<dim3(Tn / 128, Bn * Hn), 256>>>();

    // out projection: split-K=2, fused finalize+LN2
    gemm_splitk<<<dim3(Cn / 128, M / 128, 2), 256, GEMM_SMEMW * 4>>>(
        yb, whh + HOFF_O, part, Cn, Cn);
    ln2_fused<<<Bn * Tn, 256>>>(part, bo, time_gamma, x, ln2_g, ln2_b);

    // join 2: FFN needs convT_cf / convT_gw
    cudaStreamWaitEvent(0, evW2, 0);
    gemm_ffn_dual<<<dim3(FFNn / 128, M / 128), 256, DUAL_SMEMW * 4>>>(
        xmp, whh + HOFF_GK, whh + HOFF_GV, bgk, bgv, gvb);

    gemm_splitk<<<dim3(Cn / 128, M / 128, 2), 256, GEMM_SMEMW * 4>>>(
        gvb, whh + HOFF_GW, part, Cn, FFNn);
    fin_wgw<<<(M * Cn) / (256 * 4), 256>>>(part, bgw, x1, (float*)d_out);
}